// round 3
// baseline (speedup 1.0000x reference)
#include <cuda_runtime.h>

#define N_NODES 21
#define N_EDGES 23
#define D1 64
#define D2 128
#define G_TOTAL 32768
#define WARPS_PER_BLOCK 8
#define GB 8

typedef unsigned long long ull;
struct __align__(16) ull2 { ull x, y; };

__device__ __forceinline__ ull ffma2(ull a, ull b, ull c) {
    ull d;
    asm("fma.rn.f32x2 %0, %1, %2, %3;" : "=l"(d) : "l"(a), "l"(b), "l"(c));
    return d;
}
__device__ __forceinline__ ull pack2(float lo, float hi) {
    ull d;
    asm("mov.b64 %0, {%1, %2};" : "=l"(d) : "f"(lo), "f"(hi));
    return d;
}
__device__ __forceinline__ void unpack2(ull v, float& lo, float& hi) {
    asm("mov.b64 {%0, %1}, %2;" : "=f"(lo), "=f"(hi) : "l"(v));
}

__device__ __constant__ signed char c_esrc[N_EDGES] =
    {0,1,2,3, 0,5,6,7, 0,9,10,11, 0,13,14,15, 0,17,18,19, 5,9,13};
__device__ __constant__ signed char c_etgt[N_EDGES] =
    {1,2,3,4, 5,6,7,8, 9,10,11,12, 13,14,15,16, 17,18,19,20, 9,13,17};

#define R2 0.70710678118654752f
#define R3 0.57735026918962576f
__device__ __constant__ float c_dis[N_NODES] = {
    1.0f, R2, R2, R2, R2,
    R2, R2, R2, R2,
    R3, R2, R2, R2,
    R3, R2, R2, R2,
    R3, R2, R2, R2
};

// dynamic shared layout (in floats)
#define OFF_TW   0                      // [21][3] weights, pad 64
#define OFF_TI   64                     // [21][3] src indices (ints), pad 64
#define OFF_CA   128                    // [21] col accum scratch, pad 24
#define OFF_C2   152                    // [21] float2 (c/42, c/42) = 42, pad 44
#define OFF_W2   196                    // 8192 floats (16B aligned: 196*4=784)
#define OFF_WARP 8388                   // per-warp regions (16B aligned)
#define PW_X     0                      // sx8: 8 graphs * 21 * float2 = 336 floats
#define PW_Y     336                    // sy : 8 graphs * 21 * float2 = 336 floats
#define PW_V     672                    // sv : [64][8] floats = 512
#define PW_SZ    1184
#define SMEM_FLOATS (OFF_WARP + WARPS_PER_BLOCK * PW_SZ)   // 17860
#define SMEM_BYTES  (SMEM_FLOATS * 4)                       // 71440

__global__ void __launch_bounds__(256)
hand_gnn_kernel(const float* __restrict__ x,
                const float* __restrict__ W1,
                const float* __restrict__ b1,
                const float* __restrict__ W2,
                const float* __restrict__ b2,
                float* __restrict__ out)
{
    extern __shared__ float sm[];
    float* sTw = sm + OFF_TW;
    int*   sTi = (int*)(sm + OFF_TI);
    float* sCa = sm + OFF_CA;
    float2* sC2 = (float2*)(sm + OFF_C2);
    float* sW2 = sm + OFF_W2;

    const int tid = threadIdx.x;

    // ---- prolog: W2 to shared (vectorized) ----
    {
        float4* dst = (float4*)sW2;
        const float4* src = (const float4*)W2;
        for (int i = tid; i < D1 * D2 / 4; i += 256) dst[i] = src[i];
    }
    // ---- sparse table: deterministic per-node (idx, weight) lists ----
    if (tid < N_NODES) {
        int t = tid;
        float dt = c_dis[t];
        sTw[t * 3 + 0] = dt * dt;   sTi[t * 3 + 0] = t;      // self loop first
        int p = 1;
        #pragma unroll
        for (int e = 0; e < N_EDGES; e++) {
            if ((int)c_etgt[e] == t) {
                sTw[t * 3 + p] = dt * c_dis[(int)c_esrc[e]];
                sTi[t * 3 + p] = (int)c_esrc[e];
                p++;
            }
        }
        for (; p < 3; p++) { sTw[t * 3 + p] = 0.0f; sTi[t * 3 + p] = 0; }
    }
    __syncthreads();
    if (tid < N_NODES) {            // c_s = colsum of A / 21 (fixed order)
        float a = 0.0f;
        for (int i = 0; i < N_NODES * 3; i++)
            if (sTi[i] == tid) a += sTw[i];
        sCa[tid] = a;
    }
    __syncthreads();
    if (tid < N_NODES) {
        float ch = sCa[tid] * (1.0f / 42.0f);   // c_t / 2 (for relu-abs trick)
        sC2[tid] = make_float2(ch, ch);
    }
    __syncthreads();

    const int w    = tid >> 5;
    const int lane = tid & 31;
    const int g0   = (blockIdx.x * WARPS_PER_BLOCK + w) * GB;

    float* swarp = sm + OFF_WARP + w * PW_SZ;
    float* sx8 = swarp + PW_X;
    float2* sy = (float2*)(swarp + PW_Y);
    float*  sv = swarp + PW_V;

    const ull W10p = pack2(W1[lane],      W1[lane + 32]);
    const ull W11p = pack2(W1[D1 + lane], W1[D1 + lane + 32]);
    const ull B1p  = pack2(b1[lane],      b1[lane + 32]);
    const ull2 B2  = *reinterpret_cast<const ull2*>(b2 + 4 * lane);
    const ull ABSMASK = 0x7FFFFFFF7FFFFFFFull;

    // ---- load 8 graphs of x (336 floats) in one shot ----
    {
        const float4* xg = (const float4*)(x + (size_t)g0 * N_NODES * 2);
        float4* d = (float4*)sx8;
        #pragma unroll
        for (int i = lane; i < GB * N_NODES * 2 / 4; i += 32) d[i] = xg[i];
    }
    __syncwarp();

    // ---- sparse y = A @ x per graph ----
    float tw0, tw1, tw2; int ti0, ti1, ti2;
    if (lane < N_NODES) {
        tw0 = sTw[lane * 3 + 0]; ti0 = sTi[lane * 3 + 0];
        tw1 = sTw[lane * 3 + 1]; ti1 = sTi[lane * 3 + 1];
        tw2 = sTw[lane * 3 + 2]; ti2 = sTi[lane * 3 + 2];
        #pragma unroll
        for (int j = 0; j < GB; j++) {
            const float2* xj = (const float2*)(sx8 + j * N_NODES * 2);
            ull y2;
            y2 = ffma2(pack2(tw0, tw0), *(const ull*)&xj[ti0], 0ull);
            y2 = ffma2(pack2(tw1, tw1), *(const ull*)&xj[ti1], y2);
            y2 = ffma2(pack2(tw2, tw2), *(const ull*)&xj[ti2], y2);
            *(ull*)&sy[j * N_NODES + lane] = y2;
        }
    }
    __syncwarp();

    // ---- v_f = sum_t c_t * relu(y_t @ W1 + b1), t-outer / graph-inner ----
    ull vH[GB];
    #pragma unroll
    for (int j = 0; j < GB; j++) vH[j] = 0ull;

    #pragma unroll 7
    for (int t = 0; t < N_NODES; t++) {
        ull c2 = *(const ull*)&sC2[t];
        #pragma unroll
        for (int j = 0; j < GB; j++) {
            float2 yt = sy[j * N_NODES + t];
            ull y0 = pack2(yt.x, yt.x);
            ull y1 = pack2(yt.y, yt.y);
            ull h  = ffma2(y0, W10p, ffma2(y1, W11p, B1p));
            vH[j]  = ffma2(c2, h, ffma2(c2, h & ABSMASK, vH[j]));
        }
    }
    // store v: lane owns rows f=lane and f=lane+32; each row = 8 contiguous floats
    {
        float va[GB], vb[GB];
        #pragma unroll
        for (int j = 0; j < GB; j++) unpack2(vH[j], va[j], vb[j]);
        float4* r0 = (float4*)(sv + lane * GB);
        float4* r1 = (float4*)(sv + (lane + 32) * GB);
        r0[0] = make_float4(va[0], va[1], va[2], va[3]);
        r0[1] = make_float4(va[4], va[5], va[6], va[7]);
        r1[0] = make_float4(vb[0], vb[1], vb[2], vb[3]);
        r1[1] = make_float4(vb[4], vb[5], vb[6], vb[7]);
    }
    __syncwarp();

    // ---- epilogue: out = v @ W2 + b2, lane owns cols [4*lane, 4*lane+4) ----
    ull a0[GB], a1[GB];
    #pragma unroll
    for (int j = 0; j < GB; j++) { a0[j] = B2.x; a1[j] = B2.y; }

    #pragma unroll 8
    for (int f = 0; f < D1; f++) {
        ull2 q = *(const ull2*)(sW2 + f * D2 + 4 * lane);     // LDS.128
        float4 u = *(const float4*)(sv + f * GB);             // broadcast
        float4 v_ = *(const float4*)(sv + f * GB + 4);        // broadcast
        ull p0 = pack2(u.x, u.x),  p1 = pack2(u.y, u.y);
        ull p2 = pack2(u.z, u.z),  p3 = pack2(u.w, u.w);
        ull p4 = pack2(v_.x, v_.x), p5 = pack2(v_.y, v_.y);
        ull p6 = pack2(v_.z, v_.z), p7 = pack2(v_.w, v_.w);
        a0[0] = ffma2(p0, q.x, a0[0]);  a1[0] = ffma2(p0, q.y, a1[0]);
        a0[1] = ffma2(p1, q.x, a0[1]);  a1[1] = ffma2(p1, q.y, a1[1]);
        a0[2] = ffma2(p2, q.x, a0[2]);  a1[2] = ffma2(p2, q.y, a1[2]);
        a0[3] = ffma2(p3, q.x, a0[3]);  a1[3] = ffma2(p3, q.y, a1[3]);
        a0[4] = ffma2(p4, q.x, a0[4]);  a1[4] = ffma2(p4, q.y, a1[4]);
        a0[5] = ffma2(p5, q.x, a0[5]);  a1[5] = ffma2(p5, q.y, a1[5]);
        a0[6] = ffma2(p6, q.x, a0[6]);  a1[6] = ffma2(p6, q.y, a1[6]);
        a0[7] = ffma2(p7, q.x, a0[7]);  a1[7] = ffma2(p7, q.y, a1[7]);
    }

    #pragma unroll
    for (int j = 0; j < GB; j++) {
        ull2 r; r.x = a0[j]; r.y = a1[j];
        *reinterpret_cast<ull2*>(out + (size_t)(g0 + j) * D2 + 4 * lane) = r;
    }
}

extern "C" void kernel_launch(void* const* d_in, const int* in_sizes, int n_in,
                              void* d_out, int out_size) {
    const float* x  = (const float*)d_in[0];
    const float* W1 = (const float*)d_in[1];
    const float* b1 = (const float*)d_in[2];
    const float* W2 = (const float*)d_in[3];
    const float* b2 = (const float*)d_in[4];
    float* out = (float*)d_out;

    cudaFuncSetAttribute(hand_gnn_kernel,
                         cudaFuncAttributeMaxDynamicSharedMemorySize, SMEM_BYTES);

    const int blocks = G_TOTAL / (WARPS_PER_BLOCK * GB);  // 512
    hand_gnn_kernel<<<blocks, 256, SMEM_BYTES>>>(x, W1, b1, W2, b2, out);
}

// round 4
// speedup vs baseline: 1.1798x; 1.1798x over previous
#include <cuda_runtime.h>

#define N_NODES 21
#define N_EDGES 23
#define D1 64
#define D2 128
#define G_TOTAL 32768
#define WPB 16          // warps per block
#define BLOCK (WPB * 32)
#define GB 8            // graphs per warp

typedef unsigned long long ull;
struct __align__(16) ull2 { ull x, y; };

__device__ __forceinline__ ull ffma2(ull a, ull b, ull c) {
    ull d;
    asm("fma.rn.f32x2 %0, %1, %2, %3;" : "=l"(d) : "l"(a), "l"(b), "l"(c));
    return d;
}
__device__ __forceinline__ ull pack2(float lo, float hi) {
    ull d;
    asm("mov.b64 %0, {%1, %2};" : "=l"(d) : "f"(lo), "f"(hi));
    return d;
}
__device__ __forceinline__ void unpack2(ull v, float& lo, float& hi) {
    asm("mov.b64 {%0, %1}, %2;" : "=f"(lo), "=f"(hi) : "l"(v));
}

__device__ __constant__ signed char c_esrc[N_EDGES] =
    {0,1,2,3, 0,5,6,7, 0,9,10,11, 0,13,14,15, 0,17,18,19, 5,9,13};
__device__ __constant__ signed char c_etgt[N_EDGES] =
    {1,2,3,4, 5,6,7,8, 9,10,11,12, 13,14,15,16, 17,18,19,20, 9,13,17};

#define R2 0.70710678118654752f
#define R3 0.57735026918962576f
__device__ __constant__ float c_dis[N_NODES] = {
    1.0f, R2, R2, R2, R2,
    R2, R2, R2, R2,
    R3, R2, R2, R2,
    R3, R2, R2, R2,
    R3, R2, R2, R2
};

// dynamic shared layout (floats)
#define OFF_C2   0                       // float2 c/2 pairs: 42, pad 48
#define OFF_TW   48                      // [21][3] row weights: 63, pad 64
#define OFF_TI   112                     // [21][3] row src idx: 63, pad 64
#define OFF_W2   176                     // 8192 floats (176*4=704, 16B ok)
#define OFF_WARP 8368                    // 8368*4 = 33472, 16B ok
#define PW_Y     0                       // y: 8 graphs * 21 * float2 = 336
#define PW_U     336                     // union: x (336) then v[64][8] (512)
#define PW_SZ    848                     // 848*4 = 3392, 16B ok
#define SMEM_FLOATS (OFF_WARP + WPB * PW_SZ)   // 21936
#define SMEM_BYTES  (SMEM_FLOATS * 4)          // 87744

__global__ void __launch_bounds__(BLOCK, 2)
hand_gnn_kernel(const float* __restrict__ x,
                const float* __restrict__ W1,
                const float* __restrict__ b1,
                const float* __restrict__ W2,
                const float* __restrict__ b2,
                float* __restrict__ out)
{
    extern __shared__ float sm[];
    float2* sC2 = (float2*)(sm + OFF_C2);
    float*  sTw = sm + OFF_TW;
    int*    sTi = (int*)(sm + OFF_TI);
    float*  sW2 = sm + OFF_W2;

    const int tid = threadIdx.x;

    // ---- prolog: W2 -> shared; tables + c in closed form; ONE syncthreads ----
    {
        float4* dst = (float4*)sW2;
        const float4* src = (const float4*)W2;
        #pragma unroll
        for (int k = 0; k < D1 * D2 / 4 / BLOCK; k++)
            dst[tid + k * BLOCK] = src[tid + k * BLOCK];
    }
    if (tid < N_NODES) {
        const int t = tid;
        const float dt = c_dis[t];
        // row table: in-neighbors of t (self first, then edge order)
        sTw[t * 3 + 0] = dt * dt;  sTi[t * 3 + 0] = t;
        int p = 1;
        #pragma unroll
        for (int e = 0; e < N_EDGES; e++) {
            if ((int)c_etgt[e] == t) {
                sTw[t * 3 + p] = dt * c_dis[(int)c_esrc[e]];
                sTi[t * 3 + p] = (int)c_esrc[e];
                p++;
            }
        }
        for (; p < 3; p++) { sTw[t * 3 + p] = 0.0f; sTi[t * 3 + p] = 0; }
        // column sum: c_s = dis_s*(dis_s + sum_{e:src=s} dis_tgt) / 21 ; halved for abs trick
        float cs = dt;
        #pragma unroll
        for (int e = 0; e < N_EDGES; e++)
            if ((int)c_esrc[e] == t) cs += c_dis[(int)c_etgt[e]];
        float ch = dt * cs * (1.0f / 42.0f);
        sC2[t] = make_float2(ch, ch);
    }
    __syncthreads();

    const int w    = tid >> 5;
    const int lane = tid & 31;
    const int g0   = (blockIdx.x * WPB + w) * GB;

    float* swarp = sm + OFF_WARP + w * PW_SZ;
    float2* sy = (float2*)(swarp + PW_Y);
    float*  su = swarp + PW_U;          // x, later v

    const ull W10p = pack2(W1[lane],      W1[lane + 32]);
    const ull W11p = pack2(W1[D1 + lane], W1[D1 + lane + 32]);
    const ull B1p  = pack2(b1[lane],      b1[lane + 32]);
    const ull2 B2  = *reinterpret_cast<const ull2*>(b2 + 4 * lane);
    const ull ABSMASK = 0x7FFFFFFF7FFFFFFFull;

    // ---- load 8 graphs of x (336 floats, coalesced) ----
    {
        const float4* xg = (const float4*)(x + (size_t)g0 * N_NODES * 2);
        float4* d = (float4*)su;
        #pragma unroll
        for (int i = lane; i < GB * N_NODES * 2 / 4; i += 32) d[i] = xg[i];
    }
    __syncwarp();

    // ---- sparse y = A @ x per graph (lane = target node) ----
    if (lane < N_NODES) {
        const float tw0 = sTw[lane * 3 + 0]; const int ti0 = sTi[lane * 3 + 0];
        const float tw1 = sTw[lane * 3 + 1]; const int ti1 = sTi[lane * 3 + 1];
        const float tw2 = sTw[lane * 3 + 2]; const int ti2 = sTi[lane * 3 + 2];
        #pragma unroll
        for (int j = 0; j < GB; j++) {
            const float2* xj = (const float2*)(su + j * N_NODES * 2);
            ull y2;
            y2 = ffma2(pack2(tw0, tw0), *(const ull*)&xj[ti0], 0ull);
            y2 = ffma2(pack2(tw1, tw1), *(const ull*)&xj[ti1], y2);
            y2 = ffma2(pack2(tw2, tw2), *(const ull*)&xj[ti2], y2);
            *(ull*)&sy[j * N_NODES + lane] = y2;
        }
    }
    __syncwarp();

    // ---- v_f = sum_t c_t * relu(y_t @ W1 + b1); lane owns f=lane, f=lane+32 ----
    ull vH[GB];
    #pragma unroll
    for (int j = 0; j < GB; j++) vH[j] = 0ull;

    #pragma unroll 7
    for (int t = 0; t < N_NODES; t++) {
        ull c2 = *(const ull*)&sC2[t];
        #pragma unroll
        for (int j = 0; j < GB; j++) {
            float2 yt = sy[j * N_NODES + t];       // uniform broadcast
            ull y0 = pack2(yt.x, yt.x);
            ull y1 = pack2(yt.y, yt.y);
            ull h  = ffma2(y0, W10p, ffma2(y1, W11p, B1p));
            vH[j]  = ffma2(c2, h, ffma2(c2, h & ABSMASK, vH[j]));
        }
    }
    // x is dead -> write v rows over the union buffer: v[f][0..7]
    {
        float va[GB], vb[GB];
        #pragma unroll
        for (int j = 0; j < GB; j++) unpack2(vH[j], va[j], vb[j]);
        float4* r0 = (float4*)(su + lane * GB);
        float4* r1 = (float4*)(su + (lane + 32) * GB);
        r0[0] = make_float4(va[0], va[1], va[2], va[3]);
        r0[1] = make_float4(va[4], va[5], va[6], va[7]);
        r1[0] = make_float4(vb[0], vb[1], vb[2], vb[3]);
        r1[1] = make_float4(vb[4], vb[5], vb[6], vb[7]);
    }
    __syncwarp();

    // ---- epilogue: out = v @ W2 + b2; lane owns cols [4*lane, 4*lane+4) ----
    ull a0[GB], a1[GB];
    #pragma unroll
    for (int j = 0; j < GB; j++) { a0[j] = B2.x; a1[j] = B2.y; }

    #pragma unroll 8
    for (int f = 0; f < D1; f++) {
        ull2 q = *(const ull2*)(sW2 + f * D2 + 4 * lane);   // LDS.128
        float4 u = *(const float4*)(su + f * GB);           // broadcast
        float4 v_ = *(const float4*)(su + f * GB + 4);      // broadcast
        ull p0 = pack2(u.x, u.x),   p1 = pack2(u.y, u.y);
        ull p2 = pack2(u.z, u.z),   p3 = pack2(u.w, u.w);
        ull p4 = pack2(v_.x, v_.x), p5 = pack2(v_.y, v_.y);
        ull p6 = pack2(v_.z, v_.z), p7 = pack2(v_.w, v_.w);
        a0[0] = ffma2(p0, q.x, a0[0]);  a1[0] = ffma2(p0, q.y, a1[0]);
        a0[1] = ffma2(p1, q.x, a0[1]);  a1[1] = ffma2(p1, q.y, a1[1]);
        a0[2] = ffma2(p2, q.x, a0[2]);  a1[2] = ffma2(p2, q.y, a1[2]);
        a0[3] = ffma2(p3, q.x, a0[3]);  a1[3] = ffma2(p3, q.y, a1[3]);
        a0[4] = ffma2(p4, q.x, a0[4]);  a1[4] = ffma2(p4, q.y, a1[4]);
        a0[5] = ffma2(p5, q.x, a0[5]);  a1[5] = ffma2(p5, q.y, a1[5]);
        a0[6] = ffma2(p6, q.x, a0[6]);  a1[6] = ffma2(p6, q.y, a1[6]);
        a0[7] = ffma2(p7, q.x, a0[7]);  a1[7] = ffma2(p7, q.y, a1[7]);
    }

    #pragma unroll
    for (int j = 0; j < GB; j++) {
        ull2 r; r.x = a0[j]; r.y = a1[j];
        *reinterpret_cast<ull2*>(out + (size_t)(g0 + j) * D2 + 4 * lane) = r;
    }
}

extern "C" void kernel_launch(void* const* d_in, const int* in_sizes, int n_in,
                              void* d_out, int out_size) {
    const float* x  = (const float*)d_in[0];
    const float* W1 = (const float*)d_in[1];
    const float* b1 = (const float*)d_in[2];
    const float* W2 = (const float*)d_in[3];
    const float* b2 = (const float*)d_in[4];
    float* out = (float*)d_out;

    cudaFuncSetAttribute(hand_gnn_kernel,
                         cudaFuncAttributeMaxDynamicSharedMemorySize, SMEM_BYTES);

    const int blocks = G_TOTAL / (WPB * GB);   // 256 -> single wave at 2 CTAs/SM
    hand_gnn_kernel<<<blocks, BLOCK, SMEM_BYTES>>>(x, W1, b1, W2, b2, out);
}

// round 6
// speedup vs baseline: 1.7778x; 1.5069x over previous
#include <cuda_runtime.h>
#include <cuda_bf16.h>
#include <cstdint>

typedef unsigned long long ull;

#define N_NODES 21
#define N_EDGES 23
#define D1 64
#define D2 128
#define G_TOTAL 32768
#define WPB 8
#define BLOCK 256
#define GB 16               // graphs per warp
#define M_TILE 128          // graphs per CTA
#define PADK 136            // padded k-extent (bf16) -> row stride 272 B, bank spread 4
#define RSTRIDE (PADK * 2)  // 272 bytes

// ---- shared layout (float indices) ----
#define OFF_C2   0           // float2 (c/2, c/2) x21 -> 42, pad 48
#define OFF_TW   48          // [21][3] -> 63, pad to 112
#define OFF_TI   112         // [21][3] -> 63, pad to 176
#define OFF_B2   176         // b2 (128) -> 304
#define OFF_A    304         // A tile 128 x 136 bf16 = 34816 B = 8704 floats
#define OFF_B    (OFF_A + 8704)     // 9008 ; B tile 128 x 136 bf16 = 8704 floats
#define SMEM_FLOATS (OFF_B + 8704)  // 17712
#define SMEM_BYTES  (SMEM_FLOATS * 4)   // 70848

#define XW_FLOATS (GB * N_NODES * 2)    // 672 per warp (x staging, A region)
#define YW_FLOATS (GB * N_NODES * 2)    // 672 per warp (y staging, B region)

__device__ __forceinline__ ull ffma2(ull a, ull b, ull c) {
    ull d; asm("fma.rn.f32x2 %0, %1, %2, %3;" : "=l"(d) : "l"(a), "l"(b), "l"(c)); return d;
}
__device__ __forceinline__ ull pack2(float lo, float hi) {
    ull d; asm("mov.b64 %0, {%1, %2};" : "=l"(d) : "f"(lo), "f"(hi)); return d;
}
__device__ __forceinline__ void unpack2(ull v, float& lo, float& hi) {
    asm("mov.b64 {%0, %1}, %2;" : "=f"(lo), "=f"(hi) : "l"(v));
}
// d = {high=cvt(h), low=cvt(l)}
__device__ __forceinline__ uint32_t cvt_bf16x2(float h, float l) {
    uint32_t r; asm("cvt.rn.bf16x2.f32 %0, %1, %2;" : "=r"(r) : "f"(h), "f"(l)); return r;
}
__device__ __forceinline__ void mma_bf16(float& c0, float& c1, float& c2, float& c3,
                                         uint32_t a0, uint32_t a1, uint32_t a2, uint32_t a3,
                                         uint32_t b0, uint32_t b1) {
    asm("mma.sync.aligned.m16n8k16.row.col.f32.bf16.bf16.f32 "
        "{%0,%1,%2,%3}, {%4,%5,%6,%7}, {%8,%9}, {%0,%1,%2,%3};"
        : "+f"(c0), "+f"(c1), "+f"(c2), "+f"(c3)
        : "r"(a0), "r"(a1), "r"(a2), "r"(a3), "r"(b0), "r"(b1));
}

__device__ __constant__ signed char c_esrc[N_EDGES] =
    {0,1,2,3, 0,5,6,7, 0,9,10,11, 0,13,14,15, 0,17,18,19, 5,9,13};
__device__ __constant__ signed char c_etgt[N_EDGES] =
    {1,2,3,4, 5,6,7,8, 9,10,11,12, 13,14,15,16, 17,18,19,20, 9,13,17};
#define R2C 0.70710678118654752f
#define R3C 0.57735026918962576f
__device__ __constant__ float c_dis[N_NODES] = {
    1.0f, R2C, R2C, R2C, R2C,  R2C, R2C, R2C, R2C,
    R3C, R2C, R2C, R2C,  R3C, R2C, R2C, R2C,  R3C, R2C, R2C, R2C
};

__global__ void __launch_bounds__(BLOCK, 2)
hand_gnn_kernel(const float* __restrict__ x,
                const float* __restrict__ W1,
                const float* __restrict__ b1,
                const float* __restrict__ W2,
                const float* __restrict__ b2,
                float* __restrict__ out)
{
    extern __shared__ float sm[];
    char* smc = (char*)sm;
    const int tid  = threadIdx.x;
    const int w    = tid >> 5;
    const int lane = tid & 31;

    // ---- prolog: tables, c, b2 ----
    if (tid < D2) sm[OFF_B2 + tid] = b2[tid];
    if (tid < N_NODES) {
        const int t = tid;
        const float dt = c_dis[t];
        float* sTw = sm + OFF_TW;  int* sTi = (int*)(sm + OFF_TI);
        sTw[t*3+0] = dt*dt;  sTi[t*3+0] = t;
        int p = 1;
        #pragma unroll
        for (int e = 0; e < N_EDGES; e++)
            if ((int)c_etgt[e] == t) { sTw[t*3+p] = dt*c_dis[(int)c_esrc[e]]; sTi[t*3+p] = (int)c_esrc[e]; p++; }
        for (; p < 3; p++) { sTw[t*3+p] = 0.0f; sTi[t*3+p] = 0; }
        float cs = dt;
        #pragma unroll
        for (int e = 0; e < N_EDGES; e++)
            if ((int)c_esrc[e] == t) cs += c_dis[(int)c_etgt[e]];
        float ch = dt * cs * (1.0f / 42.0f);          // c_t/2 (abs-relu trick)
        ((float2*)(sm + OFF_C2))[t] = make_float2(ch, ch);
    }
    __syncthreads();

    const int g_base = blockIdx.x * M_TILE;
    const int g0w    = g_base + w * GB;

    // ---- phase 1: v[16 graphs][64 feats], lane owns feature pair (2*lane, 2*lane+1) ----
    float*  sx = sm + OFF_A + w * XW_FLOATS;          // x staging in A region
    float2* sy = (float2*)(sm + OFF_B) + w * (YW_FLOATS / 2);  // y staging in B region

    {   // coalesced x load: 672 floats / warp
        const float4* xg = (const float4*)(x + (size_t)g0w * N_NODES * 2);
        float4* d = (float4*)sx;
        #pragma unroll
        for (int i = lane; i < XW_FLOATS / 4; i += 32) d[i] = xg[i];
    }
    __syncwarp();

    if (lane < N_NODES) {   // sparse y = A @ x
        const float* sTw = sm + OFF_TW;  const int* sTi = (const int*)(sm + OFF_TI);
        const float tw0 = sTw[lane*3+0]; const int ti0 = sTi[lane*3+0];
        const float tw1 = sTw[lane*3+1]; const int ti1 = sTi[lane*3+1];
        const float tw2 = sTw[lane*3+2]; const int ti2 = sTi[lane*3+2];
        #pragma unroll 4
        for (int j = 0; j < GB; j++) {
            const float2* xj = (const float2*)(sx + j * N_NODES * 2);
            ull y2;
            y2 = ffma2(pack2(tw0, tw0), *(const ull*)&xj[ti0], 0ull);
            y2 = ffma2(pack2(tw1, tw1), *(const ull*)&xj[ti1], y2);
            y2 = ffma2(pack2(tw2, tw2), *(const ull*)&xj[ti2], y2);
            *(ull*)&sy[j * N_NODES + lane] = y2;
        }
    }
    __syncwarp();

    const ull W10p = pack2(W1[2*lane],      W1[2*lane + 1]);
    const ull W11p = pack2(W1[D1 + 2*lane], W1[D1 + 2*lane + 1]);
    const ull B1p  = pack2(b1[2*lane],      b1[2*lane + 1]);
    const ull ABSM = 0x7FFFFFFF7FFFFFFFull;

    ull vH[GB];
    #pragma unroll
    for (int j = 0; j < GB; j++) vH[j] = 0ull;
    for (int t = 0; t < N_NODES; t++) {
        const ull c2 = ((const ull*)(sm + OFF_C2))[t];
        #pragma unroll
        for (int j = 0; j < GB; j++) {
            float2 yt = sy[j * N_NODES + t];          // broadcast
            ull y0 = pack2(yt.x, yt.x);
            ull y1 = pack2(yt.y, yt.y);
            ull h  = ffma2(y0, W10p, ffma2(y1, W11p, B1p));
            vH[j]  = ffma2(c2, h, ffma2(c2, h & ABSM, vH[j]));
        }
    }
    __syncthreads();   // all x/y consumed -> A/B regions reusable

    // ---- write A tile: row = w*16+j, cols [2l,2l+1]=hi, [64+2l,64+2l+1]=lo ----
    {
        char* A = smc + OFF_A * 4;
        #pragma unroll 4
        for (int j = 0; j < GB; j++) {
            const int row = w * GB + j;
            float va, vb; unpack2(vH[j], va, vb);     // features 2l, 2l+1
            uint32_t hi2 = cvt_bf16x2(vb, va);        // low half = feature 2l
            float hia = __uint_as_float(hi2 << 16);
            float hib = __uint_as_float(hi2 & 0xFFFF0000u);
            uint32_t lo2 = cvt_bf16x2(vb - hib, va - hia);
            *(uint32_t*)(A + row * RSTRIDE + 4 * lane)       = hi2;
            *(uint32_t*)(A + row * RSTRIDE + 128 + 4 * lane) = lo2;
        }
    }

    // ---- build B tile (n-major): B[n][k]: k<64 Wh, k in 64..127 Wl ----
    {
        char* B = smc + OFF_B * 4;
        #pragma unroll
        for (int it = 0; it < 4; it++) {
            const int idx = tid + it * BLOCK;         // 1024 items
            const int fp  = idx >> 5;                 // f pair: f = 2*fp
            const int nb  = idx & 31;                 // n block: n0 = 4*nb
            float4 r0 = *(const float4*)(W2 + (2*fp)     * D2 + 4*nb);
            float4 r1 = *(const float4*)(W2 + (2*fp + 1) * D2 + 4*nb);
            const float e0[4] = {r0.x, r0.y, r0.z, r0.w};
            const float e1[4] = {r1.x, r1.y, r1.z, r1.w};
            #pragma unroll
            for (int nn = 0; nn < 4; nn++) {
                const int n = 4*nb + nn;
                float v0 = e0[nn], v1 = e1[nn];       // B[2fp][n], B[2fp+1][n]
                uint32_t hi2 = cvt_bf16x2(v1, v0);
                float h0 = __uint_as_float(hi2 << 16);
                float h1 = __uint_as_float(hi2 & 0xFFFF0000u);
                uint32_t lo2 = cvt_bf16x2(v1 - h1, v0 - h0);
                *(uint32_t*)(B + n * RSTRIDE + 4 * fp)       = hi2;
                *(uint32_t*)(B + n * RSTRIDE + 128 + 4 * fp) = lo2;
            }
        }
    }
    __syncthreads();

    // ---- epilogue: out[16x128] = A(16x[Vh|Vl]) x B([Wh|Wl]) 3-term + b2 ----
    const int r  = lane >> 2;           // group id: A row offset / B col offset
    const int tq = (lane & 3) * 2;      // k quad offset

    float c[16][4];
    #pragma unroll
    for (int m = 0; m < 16; m++) {
        float2 bb = *(const float2*)(sm + OFF_B2 + m * 8 + tq);
        c[m][0] = bb.x;  c[m][1] = bb.y;  c[m][2] = bb.x;  c[m][3] = bb.y;
    }

    const char* Arow0 = smc + OFF_A * 4 + (w * GB + r) * RSTRIDE;
    const char* Arow8 = Arow0 + 8 * RSTRIDE;
    const char* Bbase = smc + OFF_B * 4;

    #pragma unroll
    for (int s = 0; s < 12; s++) {
        // term 0: Vh x Wh (s=0..3), term 1: Vl x Wh (4..7), term 2: Vh x Wl (8..11)
        const int ks = (s & 3) * 16;
        const int ka = (s < 4) ? ks : ((s < 8) ? (64 + ks) : ks);
        const int kb = (s < 8) ? ks : (64 + ks);
        uint32_t a0 = *(const uint32_t*)(Arow0 + (ka + tq) * 2);
        uint32_t a1 = *(const uint32_t*)(Arow8 + (ka + tq) * 2);
        uint32_t a2 = *(const uint32_t*)(Arow0 + (ka + tq + 8) * 2);
        uint32_t a3 = *(const uint32_t*)(Arow8 + (ka + tq + 8) * 2);
        #pragma unroll
        for (int m = 0; m < 16; m++) {
            const char* Bn = Bbase + (m * 8 + r) * RSTRIDE;
            uint32_t b0 = *(const uint32_t*)(Bn + (kb + tq) * 2);
            uint32_t b1 = *(const uint32_t*)(Bn + (kb + tq + 8) * 2);
            mma_bf16(c[m][0], c[m][1], c[m][2], c[m][3], a0, a1, a2, a3, b0, b1);
        }
    }

    // ---- store: lane holds out[g0w+r][m*8+tq..+1] and row +8 ----
    {
        float* o0 = out + (size_t)(g0w + r) * D2;
        float* o1 = o0 + 8 * D2;
        #pragma unroll
        for (int m = 0; m < 16; m++) {
            *(float2*)(o0 + m * 8 + tq) = make_float2(c[m][0], c[m][1]);
            *(float2*)(o1 + m * 8 + tq) = make_float2(c[m][2], c[m][3]);
        }
    }
}

extern "C" void kernel_launch(void* const* d_in, const int* in_sizes, int n_in,
                              void* d_out, int out_size) {
    const float* x  = (const float*)d_in[0];
    const float* W1 = (const float*)d_in[1];
    const float* b1 = (const float*)d_in[2];
    const float* W2 = (const float*)d_in[3];
    const float* b2 = (const float*)d_in[4];
    float* out = (float*)d_out;

    cudaFuncSetAttribute(hand_gnn_kernel,
                         cudaFuncAttributeMaxDynamicSharedMemorySize, SMEM_BYTES);
    hand_gnn_kernel<<<G_TOTAL / M_TILE, BLOCK, SMEM_BYTES>>>(x, W1, b1, W2, b2, out);
}